// round 5
// baseline (speedup 1.0000x reference)
#include <cuda_runtime.h>
#include <cuda_bf16.h>
#include <cstdint>

// Problem constants
#define A_N   100000
#define B_N   200000
#define M_N   20000
#define HDIM  256
#define MAXNB 10
#define NMOLS 2000
#define AFD   35
#define KI    40    // fbonds @ W_i
#define KO    291   // [fatoms, nei] @ W_o_w

// Scratch (device globals)
__device__ float g_binput[(size_t)B_N * HDIM];
__device__ float g_msgA  [(size_t)B_N * HDIM];
__device__ float g_msgB  [(size_t)B_N * HDIM];
__device__ float g_counts[NMOLS];
// Pre-transposed, bf16-split weights: [N=256, KPAD<=320]
__device__ __nv_bfloat16 g_WThi[256 * 320];
__device__ __nv_bfloat16 g_WTlo[256 * 320];

// ---------------------------------------------------------------------------
// Helpers (all base-sm_103-legal: ldmatrix / mma.sync / cp.async)
// ---------------------------------------------------------------------------
__device__ __forceinline__ uint32_t smem_u32(const void* p) {
    uint32_t a;
    asm("{ .reg .u64 t; cvta.to.shared.u64 t, %1; cvt.u32.u64 %0, t; }" : "=r"(a) : "l"(p));
    return a;
}
__device__ __forceinline__ void ldsm4(uint32_t* r, uint32_t addr) {
    asm volatile("ldmatrix.sync.aligned.m8n8.x4.shared.b16 {%0,%1,%2,%3}, [%4];"
                 : "=r"(r[0]), "=r"(r[1]), "=r"(r[2]), "=r"(r[3]) : "r"(addr));
}
__device__ __forceinline__ void mma_bf16(float* c, const uint32_t* a, uint32_t b0, uint32_t b1) {
    asm volatile("mma.sync.aligned.m16n8k16.row.col.f32.bf16.bf16.f32 "
                 "{%0,%1,%2,%3},{%4,%5,%6,%7},{%8,%9},{%0,%1,%2,%3};"
                 : "+f"(c[0]), "+f"(c[1]), "+f"(c[2]), "+f"(c[3])
                 : "r"(a[0]), "r"(a[1]), "r"(a[2]), "r"(a[3]), "r"(b0), "r"(b1));
}
__device__ __forceinline__ void cp_async16(uint32_t dst, const void* src) {
    asm volatile("cp.async.cg.shared.global [%0], [%1], 16;" :: "r"(dst), "l"(src));
}
__device__ __forceinline__ void cp_wait_all() {
    asm volatile("cp.async.wait_all;" ::: "memory");
}

#define SW128(o) ((o) ^ ((((uint32_t)(o)) >> 3) & 0x70))

__device__ __forceinline__ void split2(float v, unsigned short& h, unsigned short& l) {
    __nv_bfloat16 hb = __float2bfloat16_rn(v);
    float rem = v - __bfloat162float(hb);
    h = __bfloat16_as_ushort(hb);
    l = __bfloat16_as_ushort(__float2bfloat16_rn(rem));
}

// ---------------------------------------------------------------------------
// Weight prep: W [Kdim, 256] fp32 -> WT hi/lo bf16 [256, Kpad] (zero padded).
// ROT=1 (output GEMM): source row = (k + AFD) % Kdim, so the gathered nei
// block lands on k=0..255 (float4-aligned) and fatoms on k=256..290.
// ---------------------------------------------------------------------------
template <int ROT>
__global__ void prep_w_kernel(const float* __restrict__ W, int Kdim, int Kpad,
                              __nv_bfloat16* __restrict__ hi, __nv_bfloat16* __restrict__ lo)
{
    int i = blockIdx.x * blockDim.x + threadIdx.x;
    if (i >= 256 * Kpad) return;
    int n = i / Kpad, k = i % Kpad;
    float v = 0.f;
    if (k < Kdim) {
        int src = ROT ? (k + AFD) % Kdim : k;
        v = __ldg(&W[(size_t)src * 256 + n]);
    }
    unsigned short h, l; split2(v, h, l);
    hi[i] = __ushort_as_bfloat16(h);
    lo[i] = __ushort_as_bfloat16(l);
}

// ---------------------------------------------------------------------------
// bf16 3-split GEMM via mma.sync with FUSED neighbor gather.
// 8 warps, 2x4 warp grid, 64x64 warp tiles over 128x256 CTA tile, K chunks
// of 64, double-buffered SW128 smem; B via cp.async; A built in registers.
// MODE 0: A = fbonds (direct)          -> out1 = C, out2 = relu(C)
// MODE 1: A = gather-sum(bgraph)       -> out1 = relu(binput + C)
// MODE 2: A = [gather-sum(agraph) | fatoms] (K rotated) ->
//            relu(C + bias) atomicAdd into out1[scope[row]]
// ---------------------------------------------------------------------------
#define OFF_ALO  16384
#define OFF_BHI  32768
#define OFF_BLO  65536
#define BUFSZ    98304
#define PTR_OFF  (2 * BUFSZ)                    // 196608
#define HG_SMEM  (PTR_OFF + 128 * MAXNB * 8)    // 206848

template <int MODE, int KDIM, int NS>
__global__ __launch_bounds__(256, 1)
void hgemm_kernel(const float* __restrict__ Amat,     // MODE0: fbonds, MODE2: fatoms
                  const int*   __restrict__ graph,    // MODE1/2 gather indices
                  const float* __restrict__ tree,
                  const float* __restrict__ msgsrc,
                  const __nv_bfloat16* __restrict__ WThi,
                  const __nv_bfloat16* __restrict__ WTlo,
                  int rowsM,
                  const float* __restrict__ binput,
                  const float* __restrict__ bias,
                  const int*   __restrict__ scope,
                  float* __restrict__ out1,
                  float* __restrict__ out2)
{
    constexpr int KPAD = NS * 64;
    extern __shared__ char smem[];
    const uint32_t sb = smem_u32(smem);
    const int tid  = threadIdx.x;
    const int lane = tid & 31, wid = tid >> 5;
    const int wm = wid & 1, wn = wid >> 1;           // 2 x 4 warp grid
    const int rowBlock = blockIdx.x * 128;
    const int r    = tid >> 1;                        // A-load row (0..127)
    const int half = tid & 1;                         // A-load col half

    // ldmatrix lane-address components
    const int arow  = ((lane >> 3) & 1) * 8 + (lane & 7);
    const int akb   = (lane >> 4) * 16;
    const int bnrow = ((lane >> 4) & 1) * 8 + (lane & 7);
    const int bkb   = ((lane >> 3) & 1) * 16;

    // Gather pointer table: 128 rows x MAXNB row-base pointers
    const float** ptab = (const float**)(smem + PTR_OFF);
    if (MODE != 0) {
#pragma unroll
        for (int i = tid; i < 128 * MAXNB; i += 256) {
            int rr = i / MAXNB, t = i % MAXNB;
            int grow = rowBlock + rr;
            const float* p = tree;   // tree row 0 is the all-zero pad vector
            if (grow < rowsM) {
                int idx = __ldg(&graph[(size_t)grow * MAXNB + t]);
                p = (idx < M_N) ? tree + (size_t)idx * HDIM
                                : msgsrc + (size_t)(idx - M_N) * HDIM;
            }
            ptab[i] = p;
        }
        __syncthreads();
    }

    float acc[4][8][4];
#pragma unroll
    for (int mi = 0; mi < 4; mi++)
#pragma unroll
        for (int ni = 0; ni < 8; ni++)
#pragma unroll
            for (int e = 0; e < 4; e++) acc[mi][ni][e] = 0.f;

    float4 af[8];

    auto ldgA = [&](int s) {
        const int k0 = s * 64;
        const int gr = rowBlock + r;
        const bool gatherSlice = (MODE == 1) || (MODE == 2 && s < 4);
        if (gatherSlice) {
#pragma unroll
            for (int j = 0; j < 8; j++) af[j] = make_float4(0.f, 0.f, 0.f, 0.f);
            const int coff = k0 + half * 32;
#pragma unroll
            for (int t = 0; t < MAXNB; t++) {
                const float4* p = (const float4*)(ptab[r * MAXNB + t] + coff);
#pragma unroll
                for (int j = 0; j < 8; j++) {
                    float4 v = __ldg(p + j);
                    af[j].x += v.x; af[j].y += v.y; af[j].z += v.z; af[j].w += v.w;
                }
            }
        } else if (MODE == 2) {
            // s == 4: fatoms columns (K rotated: col = k - 256)
#pragma unroll
            for (int j = 0; j < 8; j++) {
                float t0 = 0.f, t1 = 0.f, t2 = 0.f, t3 = 0.f;
                int c0 = half * 32 + j * 4;
                if (gr < rowsM) {
                    if (c0 + 0 < AFD) t0 = __ldg(&Amat[(size_t)gr * AFD + c0 + 0]);
                    if (c0 + 1 < AFD) t1 = __ldg(&Amat[(size_t)gr * AFD + c0 + 1]);
                    if (c0 + 2 < AFD) t2 = __ldg(&Amat[(size_t)gr * AFD + c0 + 2]);
                    if (c0 + 3 < AFD) t3 = __ldg(&Amat[(size_t)gr * AFD + c0 + 3]);
                }
                af[j] = make_float4(t0, t1, t2, t3);
            }
        } else {
            // MODE 0: direct rows from Amat [rowsM, KDIM]
#pragma unroll
            for (int j = 0; j < 8; j++) {
                int gc = k0 + half * 32 + j * 4;
                float4 v = make_float4(0.f, 0.f, 0.f, 0.f);
                if (gr < rowsM && gc < KDIM)
                    v = __ldg((const float4*)(Amat + (size_t)gr * KDIM + gc));
                af[j] = v;
            }
        }
    };

    auto stsA = [&](uint32_t bufOff) {
#pragma unroll
        for (int j = 0; j < 8; j++) {
            unsigned short h0, h1, h2, h3, l0, l1, l2, l3;
            split2(af[j].x, h0, l0); split2(af[j].y, h1, l1);
            split2(af[j].z, h2, l2); split2(af[j].w, h3, l3);
            uint2 uh, ul;
            uh.x = (uint32_t)h0 | ((uint32_t)h1 << 16);
            uh.y = (uint32_t)h2 | ((uint32_t)h3 << 16);
            ul.x = (uint32_t)l0 | ((uint32_t)l1 << 16);
            ul.y = (uint32_t)l2 | ((uint32_t)l3 << 16);
            uint32_t off = SW128(r * 128 + half * 64 + j * 8);
            *(uint2*)(smem + bufOff + off)           = uh;
            *(uint2*)(smem + bufOff + OFF_ALO + off) = ul;
        }
    };

    auto cpB = [&](int s) {
        int k0 = s * 64;
        uint32_t bufOff = (uint32_t)(s & 1) * BUFSZ;
#pragma unroll
        for (int i = 0; i < 8; i++) {
            int idx = i * 256 + tid;
            int n = idx >> 3, c = idx & 7;
            uint32_t dsw = SW128(n * 128 + c * 16);
            const __nv_bfloat16* srch = WThi + (size_t)n * KPAD + k0 + c * 8;
            const __nv_bfloat16* srcl = WTlo + (size_t)n * KPAD + k0 + c * 8;
            cp_async16(sb + bufOff + OFF_BHI + dsw, srch);
            cp_async16(sb + bufOff + OFF_BLO + dsw, srcl);
        }
    };

    // Prologue
    ldgA(0);
    cpB(0);

    for (int s = 0; s < NS; s++) {
        uint32_t bufOff = (uint32_t)(s & 1) * BUFSZ;
        cp_wait_all();              // B(s) arrived
        stsA(bufOff);
        __syncthreads();            // smem tile visible to all
        if (s + 1 < NS) { cpB(s + 1); ldgA(s + 1); }

        const uint32_t aBase = sb + bufOff;
#pragma unroll
        for (int kk = 0; kk < 4; kk++) {
            uint32_t ahi[4][4], alo[4][4];
#pragma unroll
            for (int mi = 0; mi < 4; mi++) {
                uint32_t off = (uint32_t)(wm * 64 + mi * 16 + arow) * 128 + kk * 32 + akb;
                uint32_t sw = SW128(off);
                ldsm4(ahi[mi], aBase + sw);
                ldsm4(alo[mi], aBase + OFF_ALO + sw);
            }
#pragma unroll
            for (int nb = 0; nb < 4; nb++) {
                uint32_t off = (uint32_t)(wn * 64 + nb * 16 + bnrow) * 128 + kk * 32 + bkb;
                uint32_t sw = SW128(off);
                uint32_t bh[4], bl[4];
                ldsm4(bh, aBase + OFF_BHI + sw);
                ldsm4(bl, aBase + OFF_BLO + sw);
#pragma unroll
                for (int mi = 0; mi < 4; mi++) {
                    mma_bf16(acc[mi][2*nb],   ahi[mi], bh[0], bh[1]);
                    mma_bf16(acc[mi][2*nb+1], ahi[mi], bh[2], bh[3]);
                    mma_bf16(acc[mi][2*nb],   alo[mi], bh[0], bh[1]);
                    mma_bf16(acc[mi][2*nb+1], alo[mi], bh[2], bh[3]);
                    mma_bf16(acc[mi][2*nb],   ahi[mi], bl[0], bl[1]);
                    mma_bf16(acc[mi][2*nb+1], ahi[mi], bl[2], bl[3]);
                }
            }
        }
    }

    // ---- Epilogue: acc in registers ----
#pragma unroll
    for (int mi = 0; mi < 4; mi++) {
        int r0 = rowBlock + wm * 64 + mi * 16 + (lane >> 2);
        int r1 = r0 + 8;
        int seg0 = 0, seg1 = 0;
        if (MODE == 2) {
            seg0 = (r0 < rowsM) ? __ldg(&scope[r0]) : 0;
            seg1 = (r1 < rowsM) ? __ldg(&scope[r1]) : 0;
        }
#pragma unroll
        for (int ni = 0; ni < 8; ni++) {
            int col = wn * 64 + ni * 8 + (lane & 3) * 2;
            float* c = acc[mi][ni];
            if (MODE == 0) {
                if (r0 < rowsM) {
                    size_t p = (size_t)r0 * HDIM + col;
                    *(float2*)(out1 + p) = make_float2(c[0], c[1]);
                    *(float2*)(out2 + p) = make_float2(fmaxf(c[0],0.f), fmaxf(c[1],0.f));
                }
                if (r1 < rowsM) {
                    size_t p = (size_t)r1 * HDIM + col;
                    *(float2*)(out1 + p) = make_float2(c[2], c[3]);
                    *(float2*)(out2 + p) = make_float2(fmaxf(c[2],0.f), fmaxf(c[3],0.f));
                }
            } else if (MODE == 1) {
                if (r0 < rowsM) {
                    size_t p = (size_t)r0 * HDIM + col;
                    float2 b = *(const float2*)(binput + p);
                    *(float2*)(out1 + p) = make_float2(fmaxf(c[0]+b.x,0.f), fmaxf(c[1]+b.y,0.f));
                }
                if (r1 < rowsM) {
                    size_t p = (size_t)r1 * HDIM + col;
                    float2 b = *(const float2*)(binput + p);
                    *(float2*)(out1 + p) = make_float2(fmaxf(c[2]+b.x,0.f), fmaxf(c[3]+b.y,0.f));
                }
            } else {
                float b0 = __ldg(&bias[col]), b1 = __ldg(&bias[col + 1]);
                if (r0 < rowsM) {
                    atomicAdd(&out1[(size_t)seg0 * HDIM + col],     fmaxf(c[0] + b0, 0.f));
                    atomicAdd(&out1[(size_t)seg0 * HDIM + col + 1], fmaxf(c[1] + b1, 0.f));
                }
                if (r1 < rowsM) {
                    atomicAdd(&out1[(size_t)seg1 * HDIM + col],     fmaxf(c[2] + b0, 0.f));
                    atomicAdd(&out1[(size_t)seg1 * HDIM + col + 1], fmaxf(c[3] + b1, 0.f));
                }
            }
        }
    }
}

// ---------------------------------------------------------------------------
// Pooling helpers
// ---------------------------------------------------------------------------
__global__ void zero_out_kernel(float* __restrict__ out)
{
    int i = blockIdx.x * blockDim.x + threadIdx.x;
    if (i < NMOLS * HDIM) out[i] = 0.f;
    if (i < NMOLS) g_counts[i] = 0.f;
}
__global__ void count_kernel(const int* __restrict__ scope)
{
    int i = blockIdx.x * blockDim.x + threadIdx.x;
    if (i < A_N) atomicAdd(&g_counts[__ldg(&scope[i])], 1.f);
}
__global__ void finalize_kernel(float* __restrict__ out)
{
    int i = blockIdx.x * blockDim.x + threadIdx.x;
    if (i >= NMOLS * HDIM) return;
    out[i] = out[i] / fmaxf(g_counts[i / HDIM], 1.f);
}

// ---------------------------------------------------------------------------
extern "C" void kernel_launch(void* const* d_in, const int* in_sizes, int n_in,
                              void* d_out, int out_size)
{
    const float* fatoms   = (const float*)d_in[0];
    const float* fbonds   = (const float*)d_in[1];
    const int*   agraph   = (const int*)  d_in[2];
    const int*   bgraph   = (const int*)  d_in[3];
    const float* tree_msg = (const float*)d_in[4];
    const int*   scope    = (const int*)  d_in[5];
    const float* W_i      = (const float*)d_in[6];
    const float* W_h      = (const float*)d_in[7];
    const float* W_o_w    = (const float*)d_in[8];
    const float* W_o_b    = (const float*)d_in[9];
    float* out = (float*)d_out;

    float *binput, *msgA, *msgB;
    __nv_bfloat16 *wthi, *wtlo;
    cudaGetSymbolAddress((void**)&binput, g_binput);
    cudaGetSymbolAddress((void**)&msgA,   g_msgA);
    cudaGetSymbolAddress((void**)&msgB,   g_msgB);
    cudaGetSymbolAddress((void**)&wthi,   g_WThi);
    cudaGetSymbolAddress((void**)&wtlo,   g_WTlo);

    cudaFuncSetAttribute(hgemm_kernel<0, KI,   1>, cudaFuncAttributeMaxDynamicSharedMemorySize, HG_SMEM);
    cudaFuncSetAttribute(hgemm_kernel<1, HDIM, 4>, cudaFuncAttributeMaxDynamicSharedMemorySize, HG_SMEM);
    cudaFuncSetAttribute(hgemm_kernel<2, KO,   5>, cudaFuncAttributeMaxDynamicSharedMemorySize, HG_SMEM);

    const int gridB = (B_N + 127) / 128;   // 1563
    const int gridA = (A_N + 127) / 128;   // 782

    // 1) binput = fbonds @ W_i ; msgA = relu(binput)
    prep_w_kernel<0><<<(256 * 64 + 255) / 256, 256>>>(W_i, KI, 64, wthi, wtlo);
    hgemm_kernel<0, KI, 1><<<gridB, 256, HG_SMEM>>>(
        fbonds, nullptr, tree_msg, nullptr, wthi, wtlo, B_N,
        nullptr, nullptr, nullptr, binput, msgA);

    // 2) two message-passing iterations, gather fused into GEMM A-load
    prep_w_kernel<0><<<(256 * 256 + 255) / 256, 256>>>(W_h, HDIM, 256, wthi, wtlo);
    hgemm_kernel<1, HDIM, 4><<<gridB, 256, HG_SMEM>>>(
        nullptr, bgraph, tree_msg, msgA, wthi, wtlo, B_N,
        binput, nullptr, nullptr, msgB, nullptr);
    hgemm_kernel<1, HDIM, 4><<<gridB, 256, HG_SMEM>>>(
        nullptr, bgraph, tree_msg, msgB, wthi, wtlo, B_N,
        binput, nullptr, nullptr, msgA, nullptr);

    // 3) pooling prep + output GEMM with fused atom gather + segment-sum
    zero_out_kernel<<<(NMOLS * HDIM + 255) / 256, 256>>>(out);
    count_kernel<<<(A_N + 255) / 256, 256>>>(scope);
    prep_w_kernel<1><<<(256 * 320 + 255) / 256, 256>>>(W_o_w, KO, 320, wthi, wtlo);
    hgemm_kernel<2, KO, 5><<<gridA, 256, HG_SMEM>>>(
        fatoms, agraph, tree_msg, msgA, wthi, wtlo, A_N,
        nullptr, W_o_b, scope, out, nullptr);
    finalize_kernel<<<(NMOLS * HDIM + 255) / 256, 256>>>(out);
}

// round 6
// speedup vs baseline: 1.5900x; 1.5900x over previous
#include <cuda_runtime.h>
#include <cuda_bf16.h>
#include <cstdint>

// Problem constants
#define A_N   100000
#define B_N   200000
#define M_N   20000
#define HDIM  256
#define MAXNB 10
#define NMOLS 2000
#define AFD   35
#define KI    40    // fbonds @ W_i
#define KO    291   // [fatoms, nei] @ W_o_w

// Scratch (device globals)
__device__ float g_binput[(size_t)B_N * HDIM];
__device__ float g_msgA  [(size_t)B_N * HDIM];
__device__ float g_msgB  [(size_t)B_N * HDIM];
__device__ float g_counts[NMOLS];
// Pre-transposed, bf16-split weights: [N=256, KPAD<=320]
__device__ __nv_bfloat16 g_WThi[256 * 320];
__device__ __nv_bfloat16 g_WTlo[256 * 320];

// ---------------------------------------------------------------------------
// Helpers (base-sm_103-legal: ldmatrix / mma.sync / cp.async)
// ---------------------------------------------------------------------------
__device__ __forceinline__ uint32_t smem_u32(const void* p) {
    uint32_t a;
    asm("{ .reg .u64 t; cvta.to.shared.u64 t, %1; cvt.u32.u64 %0, t; }" : "=r"(a) : "l"(p));
    return a;
}
__device__ __forceinline__ void ldsm4(uint32_t* r, uint32_t addr) {
    asm volatile("ldmatrix.sync.aligned.m8n8.x4.shared.b16 {%0,%1,%2,%3}, [%4];"
                 : "=r"(r[0]), "=r"(r[1]), "=r"(r[2]), "=r"(r[3]) : "r"(addr));
}
__device__ __forceinline__ void mma_bf16(float* c, const uint32_t* a, uint32_t b0, uint32_t b1) {
    asm volatile("mma.sync.aligned.m16n8k16.row.col.f32.bf16.bf16.f32 "
                 "{%0,%1,%2,%3},{%4,%5,%6,%7},{%8,%9},{%0,%1,%2,%3};"
                 : "+f"(c[0]), "+f"(c[1]), "+f"(c[2]), "+f"(c[3])
                 : "r"(a[0]), "r"(a[1]), "r"(a[2]), "r"(a[3]), "r"(b0), "r"(b1));
}
__device__ __forceinline__ void cp_async16(uint32_t dst, const void* src) {
    asm volatile("cp.async.cg.shared.global [%0], [%1], 16;" :: "r"(dst), "l"(src));
}
__device__ __forceinline__ void cp_wait_all() {
    asm volatile("cp.async.wait_all;" ::: "memory");
}

#define SW128(o) ((o) ^ ((((uint32_t)(o)) >> 3) & 0x70))

__device__ __forceinline__ void split2(float v, unsigned short& h, unsigned short& l) {
    __nv_bfloat16 hb = __float2bfloat16_rn(v);
    float rem = v - __bfloat162float(hb);
    h = __bfloat16_as_ushort(hb);
    l = __bfloat16_as_ushort(__float2bfloat16_rn(rem));
}

// ---------------------------------------------------------------------------
// Weight prep: W [Kdim, 256] fp32 -> WT hi/lo bf16 [256, Kpad] (zero padded).
// ROT=1 (output GEMM): source row = (k + AFD) % Kdim, so the gathered nei
// block lands on k=0..255 (float4-aligned) and fatoms on k=256..290.
// ---------------------------------------------------------------------------
template <int ROT>
__global__ void prep_w_kernel(const float* __restrict__ W, int Kdim, int Kpad,
                              __nv_bfloat16* __restrict__ hi, __nv_bfloat16* __restrict__ lo)
{
    int i = blockIdx.x * blockDim.x + threadIdx.x;
    if (i >= 256 * Kpad) return;
    int n = i / Kpad, k = i % Kpad;
    float v = 0.f;
    if (k < Kdim) {
        int src = ROT ? (k + AFD) % Kdim : k;
        v = __ldg(&W[(size_t)src * 256 + n]);
    }
    unsigned short h, l; split2(v, h, l);
    hi[i] = __ushort_as_bfloat16(h);
    lo[i] = __ushort_as_bfloat16(l);
}

// ---------------------------------------------------------------------------
// bf16 3-split GEMM via mma.sync with FUSED neighbor gather.
// 512 threads, 16 warps in 2(M)x8(N) grid, 64x32 warp tiles over a 128x256
// CTA tile; K chunks of 64, double-buffered SW128 smem; B via cp.async;
// A gathered/built in registers (low footprint: acc=64 regs, af=16 regs).
// MODE 0: A = fbonds (direct)          -> out1 = C, out2 = relu(C)
// MODE 1: A = gather-sum(bgraph)       -> out1 = relu(binput + C)
// MODE 2: A = [gather-sum(agraph) | fatoms] (K rotated) ->
//            relu(C + bias) atomicAdd into out1[scope[row]]
// ---------------------------------------------------------------------------
#define OFF_ALO  16384
#define OFF_BHI  32768
#define OFF_BLO  65536
#define BUFSZ    98304
#define PTR_OFF  (2 * BUFSZ)                    // 196608
#define HG_SMEM  (PTR_OFF + 128 * MAXNB * 8)    // 206848

template <int MODE, int KDIM, int NS>
__global__ __launch_bounds__(512, 1)
void hgemm_kernel(const float* __restrict__ Amat,     // MODE0: fbonds, MODE2: fatoms
                  const int*   __restrict__ graph,    // MODE1/2 gather indices
                  const float* __restrict__ tree,
                  const float* __restrict__ msgsrc,
                  const __nv_bfloat16* __restrict__ WThi,
                  const __nv_bfloat16* __restrict__ WTlo,
                  int rowsM,
                  const float* __restrict__ binput,
                  const float* __restrict__ bias,
                  const int*   __restrict__ scope,
                  float* __restrict__ out1,
                  float* __restrict__ out2)
{
    constexpr int KPAD = NS * 64;
    extern __shared__ char smem[];
    const uint32_t sb = smem_u32(smem);
    const int tid  = threadIdx.x;
    const int lane = tid & 31, wid = tid >> 5;
    const int wm = wid & 1, wn = wid >> 1;            // 2 x 8 warp grid
    const int rowBlock = blockIdx.x * 128;
    const int r = tid >> 2;                            // A-load row (0..127)
    const int q = tid & 3;                             // A-load col quarter (16 cols)

    // ldmatrix lane-address components
    const int arow  = ((lane >> 3) & 1) * 8 + (lane & 7);
    const int akb   = (lane >> 4) * 16;
    const int bnrow = ((lane >> 4) & 1) * 8 + (lane & 7);
    const int bkb   = ((lane >> 3) & 1) * 16;

    // Gather pointer table: 128 rows x MAXNB row-base pointers
    const float** ptab = (const float**)(smem + PTR_OFF);
    if (MODE != 0) {
        for (int i = tid; i < 128 * MAXNB; i += 512) {
            int rr = i / MAXNB, t = i % MAXNB;
            int grow = rowBlock + rr;
            const float* p = tree;   // tree row 0 is the all-zero pad vector
            if (grow < rowsM) {
                int idx = __ldg(&graph[(size_t)grow * MAXNB + t]);
                p = (idx < M_N) ? tree + (size_t)idx * HDIM
                                : msgsrc + (size_t)(idx - M_N) * HDIM;
            }
            ptab[i] = p;
        }
        __syncthreads();
    }

    float acc[4][4][4];   // [mi][ni(8cols)][quad]
#pragma unroll
    for (int mi = 0; mi < 4; mi++)
#pragma unroll
        for (int ni = 0; ni < 4; ni++)
#pragma unroll
            for (int e = 0; e < 4; e++) acc[mi][ni][e] = 0.f;

    float4 af[4];

    auto ldgA = [&](int s) {
        const int k0 = s * 64;
        const int gr = rowBlock + r;
        const bool gatherSlice = (MODE == 1) || (MODE == 2 && s < 4);
        if (gatherSlice) {
#pragma unroll
            for (int j = 0; j < 4; j++) af[j] = make_float4(0.f, 0.f, 0.f, 0.f);
            const int coff = k0 + q * 16;
#pragma unroll
            for (int t = 0; t < MAXNB; t++) {
                const float4* p = (const float4*)(ptab[r * MAXNB + t] + coff);
#pragma unroll
                for (int j = 0; j < 4; j++) {
                    float4 v = __ldg(p + j);
                    af[j].x += v.x; af[j].y += v.y; af[j].z += v.z; af[j].w += v.w;
                }
            }
        } else if (MODE == 2) {
            // s == 4: fatoms columns (K rotated: col = k - 256)
#pragma unroll
            for (int j = 0; j < 4; j++) {
                float t0 = 0.f, t1 = 0.f, t2 = 0.f, t3 = 0.f;
                int c0 = q * 16 + j * 4;
                if (gr < rowsM) {
                    if (c0 + 0 < AFD) t0 = __ldg(&Amat[(size_t)gr * AFD + c0 + 0]);
                    if (c0 + 1 < AFD) t1 = __ldg(&Amat[(size_t)gr * AFD + c0 + 1]);
                    if (c0 + 2 < AFD) t2 = __ldg(&Amat[(size_t)gr * AFD + c0 + 2]);
                    if (c0 + 3 < AFD) t3 = __ldg(&Amat[(size_t)gr * AFD + c0 + 3]);
                }
                af[j] = make_float4(t0, t1, t2, t3);
            }
        } else {
            // MODE 0: direct rows from Amat [rowsM, KDIM]
#pragma unroll
            for (int j = 0; j < 4; j++) {
                int gc = k0 + q * 16 + j * 4;
                float4 v = make_float4(0.f, 0.f, 0.f, 0.f);
                if (gr < rowsM && gc < KDIM)
                    v = __ldg((const float4*)(Amat + (size_t)gr * KDIM + gc));
                af[j] = v;
            }
        }
    };

    auto stsA = [&](uint32_t bufOff) {
#pragma unroll
        for (int j = 0; j < 4; j++) {
            unsigned short h0, h1, h2, h3, l0, l1, l2, l3;
            split2(af[j].x, h0, l0); split2(af[j].y, h1, l1);
            split2(af[j].z, h2, l2); split2(af[j].w, h3, l3);
            uint2 uh, ul;
            uh.x = (uint32_t)h0 | ((uint32_t)h1 << 16);
            uh.y = (uint32_t)h2 | ((uint32_t)h3 << 16);
            ul.x = (uint32_t)l0 | ((uint32_t)l1 << 16);
            ul.y = (uint32_t)l2 | ((uint32_t)l3 << 16);
            uint32_t off = SW128(r * 128 + q * 32 + j * 8);
            *(uint2*)(smem + bufOff + off)           = uh;
            *(uint2*)(smem + bufOff + OFF_ALO + off) = ul;
        }
    };

    auto cpB = [&](int s) {
        int k0 = s * 64;
        uint32_t bufOff = (uint32_t)(s & 1) * BUFSZ;
#pragma unroll
        for (int i = 0; i < 4; i++) {
            int idx = i * 512 + tid;                 // 2048 16B-chunks per half
            int n = idx >> 3, c = idx & 7;
            uint32_t dsw = SW128(n * 128 + c * 16);
            const __nv_bfloat16* srch = WThi + (size_t)n * KPAD + k0 + c * 8;
            const __nv_bfloat16* srcl = WTlo + (size_t)n * KPAD + k0 + c * 8;
            cp_async16(sb + bufOff + OFF_BHI + dsw, srch);
            cp_async16(sb + bufOff + OFF_BLO + dsw, srcl);
        }
    };

    // Prologue
    ldgA(0);
    cpB(0);

    for (int s = 0; s < NS; s++) {
        uint32_t bufOff = (uint32_t)(s & 1) * BUFSZ;
        cp_wait_all();              // B(s) arrived
        stsA(bufOff);
        __syncthreads();            // smem tile visible to all
        if (s + 1 < NS) { cpB(s + 1); ldgA(s + 1); }

        const uint32_t aBase = sb + bufOff;
#pragma unroll
        for (int kk = 0; kk < 4; kk++) {
#pragma unroll
            for (int nb = 0; nb < 2; nb++) {       // 2 x 16-col blocks
                uint32_t boff = (uint32_t)(wn * 32 + nb * 16 + bnrow) * 128 + kk * 32 + bkb;
                uint32_t bsw = SW128(boff);
                uint32_t bh[4], bl[4];
                ldsm4(bh, aBase + OFF_BHI + bsw);
                ldsm4(bl, aBase + OFF_BLO + bsw);
#pragma unroll
                for (int mi = 0; mi < 4; mi++) {
                    uint32_t aoff = (uint32_t)(wm * 64 + mi * 16 + arow) * 128 + kk * 32 + akb;
                    uint32_t asw = SW128(aoff);
                    uint32_t ahi[4], alo[4];
                    ldsm4(ahi, aBase + asw);
                    ldsm4(alo, aBase + OFF_ALO + asw);
                    mma_bf16(acc[mi][2*nb],   ahi, bh[0], bh[1]);
                    mma_bf16(acc[mi][2*nb+1], ahi, bh[2], bh[3]);
                    mma_bf16(acc[mi][2*nb],   alo, bh[0], bh[1]);
                    mma_bf16(acc[mi][2*nb+1], alo, bh[2], bh[3]);
                    mma_bf16(acc[mi][2*nb],   ahi, bl[0], bl[1]);
                    mma_bf16(acc[mi][2*nb+1], ahi, bl[2], bl[3]);
                }
            }
        }
    }

    // ---- Epilogue: acc in registers ----
#pragma unroll
    for (int mi = 0; mi < 4; mi++) {
        int r0 = rowBlock + wm * 64 + mi * 16 + (lane >> 2);
        int r1 = r0 + 8;
        int seg0 = 0, seg1 = 0;
        if (MODE == 2) {
            seg0 = (r0 < rowsM) ? __ldg(&scope[r0]) : 0;
            seg1 = (r1 < rowsM) ? __ldg(&scope[r1]) : 0;
        }
#pragma unroll
        for (int ni = 0; ni < 4; ni++) {
            int col = wn * 32 + ni * 8 + (lane & 3) * 2;
            float* c = acc[mi][ni];
            if (MODE == 0) {
                if (r0 < rowsM) {
                    size_t p = (size_t)r0 * HDIM + col;
                    *(float2*)(out1 + p) = make_float2(c[0], c[1]);
                    *(float2*)(out2 + p) = make_float2(fmaxf(c[0],0.f), fmaxf(c[1],0.f));
                }
                if (r1 < rowsM) {
                    size_t p = (size_t)r1 * HDIM + col;
                    *(float2*)(out1 + p) = make_float2(c[2], c[3]);
                    *(float2*)(out2 + p) = make_float2(fmaxf(c[2],0.f), fmaxf(c[3],0.f));
                }
            } else if (MODE == 1) {
                if (r0 < rowsM) {
                    size_t p = (size_t)r0 * HDIM + col;
                    float2 b = *(const float2*)(binput + p);
                    *(float2*)(out1 + p) = make_float2(fmaxf(c[0]+b.x,0.f), fmaxf(c[1]+b.y,0.f));
                }
                if (r1 < rowsM) {
                    size_t p = (size_t)r1 * HDIM + col;
                    float2 b = *(const float2*)(binput + p);
                    *(float2*)(out1 + p) = make_float2(fmaxf(c[2]+b.x,0.f), fmaxf(c[3]+b.y,0.f));
                }
            } else {
                float b0 = __ldg(&bias[col]), b1 = __ldg(&bias[col + 1]);
                if (r0 < rowsM) {
                    atomicAdd(&out1[(size_t)seg0 * HDIM + col],     fmaxf(c[0] + b0, 0.f));
                    atomicAdd(&out1[(size_t)seg0 * HDIM + col + 1], fmaxf(c[1] + b1, 0.f));
                }
                if (r1 < rowsM) {
                    atomicAdd(&out1[(size_t)seg1 * HDIM + col],     fmaxf(c[2] + b0, 0.f));
                    atomicAdd(&out1[(size_t)seg1 * HDIM + col + 1], fmaxf(c[3] + b1, 0.f));
                }
            }
        }
    }
}

// ---------------------------------------------------------------------------
// Pooling helpers
// ---------------------------------------------------------------------------
__global__ void zero_out_kernel(float* __restrict__ out)
{
    int i = blockIdx.x * blockDim.x + threadIdx.x;
    if (i < NMOLS * HDIM) out[i] = 0.f;
    if (i < NMOLS) g_counts[i] = 0.f;
}
__global__ void count_kernel(const int* __restrict__ scope)
{
    int i = blockIdx.x * blockDim.x + threadIdx.x;
    if (i < A_N) atomicAdd(&g_counts[__ldg(&scope[i])], 1.f);
}
__global__ void finalize_kernel(float* __restrict__ out)
{
    int i = blockIdx.x * blockDim.x + threadIdx.x;
    if (i >= NMOLS * HDIM) return;
    out[i] = out[i] / fmaxf(g_counts[i / HDIM], 1.f);
}

// ---------------------------------------------------------------------------
extern "C" void kernel_launch(void* const* d_in, const int* in_sizes, int n_in,
                              void* d_out, int out_size)
{
    const float* fatoms   = (const float*)d_in[0];
    const float* fbonds   = (const float*)d_in[1];
    const int*   agraph   = (const int*)  d_in[2];
    const int*   bgraph   = (const int*)  d_in[3];
    const float* tree_msg = (const float*)d_in[4];
    const int*   scope    = (const int*)  d_in[5];
    const float* W_i      = (const float*)d_in[6];
    const float* W_h      = (const float*)d_in[7];
    const float* W_o_w    = (const float*)d_in[8];
    const float* W_o_b    = (const float*)d_in[9];
    float* out = (float*)d_out;

    float *binput, *msgA, *msgB;
    __nv_bfloat16 *wthi, *wtlo;
    cudaGetSymbolAddress((void**)&binput, g_binput);
    cudaGetSymbolAddress((void**)&msgA,   g_msgA);
    cudaGetSymbolAddress((void**)&msgB,   g_msgB);
    cudaGetSymbolAddress((void**)&wthi,   g_WThi);
    cudaGetSymbolAddress((void**)&wtlo,   g_WTlo);

    cudaFuncSetAttribute(hgemm_kernel<0, KI,   1>, cudaFuncAttributeMaxDynamicSharedMemorySize, HG_SMEM);
    cudaFuncSetAttribute(hgemm_kernel<1, HDIM, 4>, cudaFuncAttributeMaxDynamicSharedMemorySize, HG_SMEM);
    cudaFuncSetAttribute(hgemm_kernel<2, KO,   5>, cudaFuncAttributeMaxDynamicSharedMemorySize, HG_SMEM);

    const int gridB = (B_N + 127) / 128;   // 1563
    const int gridA = (A_N + 127) / 128;   // 782

    // 1) binput = fbonds @ W_i ; msgA = relu(binput)
    prep_w_kernel<0><<<(256 * 64 + 255) / 256, 256>>>(W_i, KI, 64, wthi, wtlo);
    hgemm_kernel<0, KI, 1><<<gridB, 512, HG_SMEM>>>(
        fbonds, nullptr, tree_msg, nullptr, wthi, wtlo, B_N,
        nullptr, nullptr, nullptr, binput, msgA);

    // 2) two message-passing iterations, gather fused into GEMM A-load
    prep_w_kernel<0><<<(256 * 256 + 255) / 256, 256>>>(W_h, HDIM, 256, wthi, wtlo);
    hgemm_kernel<1, HDIM, 4><<<gridB, 512, HG_SMEM>>>(
        nullptr, bgraph, tree_msg, msgA, wthi, wtlo, B_N,
        binput, nullptr, nullptr, msgB, nullptr);
    hgemm_kernel<1, HDIM, 4><<<gridB, 512, HG_SMEM>>>(
        nullptr, bgraph, tree_msg, msgB, wthi, wtlo, B_N,
        binput, nullptr, nullptr, msgA, nullptr);

    // 3) pooling prep + output GEMM with fused atom gather + segment-sum
    zero_out_kernel<<<(NMOLS * HDIM + 255) / 256, 256>>>(out);
    count_kernel<<<(A_N + 255) / 256, 256>>>(scope);
    prep_w_kernel<1><<<(256 * 320 + 255) / 256, 256>>>(W_o_w, KO, 320, wthi, wtlo);
    hgemm_kernel<2, KO, 5><<<gridA, 512, HG_SMEM>>>(
        fatoms, agraph, tree_msg, msgA, wthi, wtlo, A_N,
        nullptr, W_o_b, scope, out, nullptr);
    finalize_kernel<<<(NMOLS * HDIM + 255) / 256, 256>>>(out);
}

// round 7
// speedup vs baseline: 1.8552x; 1.1668x over previous
#include <cuda_runtime.h>
#include <cuda_bf16.h>
#include <cstdint>

// Problem constants
#define A_N   100000
#define B_N   200000
#define M_N   20000
#define HDIM  256
#define MAXNB 10
#define NMOLS 2000
#define AFD   35
#define KI    40    // fbonds @ W_i
#define KO    291   // [fatoms, nei] @ W_o_w

// Scratch (device globals)
__device__ float g_binput[(size_t)B_N * HDIM];
__device__ float g_msgA  [(size_t)B_N * HDIM];
__device__ float g_msgB  [(size_t)B_N * HDIM];
__device__ float g_counts[NMOLS];
// Pre-transposed, bf16-split weights: [N=256, KPAD<=320]
__device__ __nv_bfloat16 g_WThi[256 * 320];
__device__ __nv_bfloat16 g_WTlo[256 * 320];

// ---------------------------------------------------------------------------
// Helpers (base-sm_103-legal: ldmatrix / mma.sync / cp.async)
// ---------------------------------------------------------------------------
__device__ __forceinline__ uint32_t smem_u32(const void* p) {
    uint32_t a;
    asm("{ .reg .u64 t; cvta.to.shared.u64 t, %1; cvt.u32.u64 %0, t; }" : "=r"(a) : "l"(p));
    return a;
}
__device__ __forceinline__ void ldsm4(uint32_t* r, uint32_t addr) {
    asm volatile("ldmatrix.sync.aligned.m8n8.x4.shared.b16 {%0,%1,%2,%3}, [%4];"
                 : "=r"(r[0]), "=r"(r[1]), "=r"(r[2]), "=r"(r[3]) : "r"(addr));
}
__device__ __forceinline__ void mma_bf16(float* c, const uint32_t* a, uint32_t b0, uint32_t b1) {
    asm volatile("mma.sync.aligned.m16n8k16.row.col.f32.bf16.bf16.f32 "
                 "{%0,%1,%2,%3},{%4,%5,%6,%7},{%8,%9},{%0,%1,%2,%3};"
                 : "+f"(c[0]), "+f"(c[1]), "+f"(c[2]), "+f"(c[3])
                 : "r"(a[0]), "r"(a[1]), "r"(a[2]), "r"(a[3]), "r"(b0), "r"(b1));
}
__device__ __forceinline__ void cp_async16(uint32_t dst, const void* src) {
    asm volatile("cp.async.cg.shared.global [%0], [%1], 16;" :: "r"(dst), "l"(src));
}
__device__ __forceinline__ void cp_wait_all() {
    asm volatile("cp.async.wait_all;" ::: "memory");
}

#define SW128(o) ((o) ^ ((((uint32_t)(o)) >> 3) & 0x70))

__device__ __forceinline__ void split2(float v, unsigned short& h, unsigned short& l) {
    __nv_bfloat16 hb = __float2bfloat16_rn(v);
    float rem = v - __bfloat162float(hb);
    h = __bfloat16_as_ushort(hb);
    l = __bfloat16_as_ushort(__float2bfloat16_rn(rem));
}

// ---------------------------------------------------------------------------
// Weight prep: W [Kdim, 256] fp32 -> WT hi/lo bf16 [256, Kpad] (zero padded).
// ROT=1 (output GEMM): source row = (k + AFD) % Kdim, so the gathered nei
// block lands on k=0..255 (float4-aligned) and fatoms on k=256..290.
// ---------------------------------------------------------------------------
template <int ROT>
__global__ void prep_w_kernel(const float* __restrict__ W, int Kdim, int Kpad,
                              __nv_bfloat16* __restrict__ hi, __nv_bfloat16* __restrict__ lo)
{
    int i = blockIdx.x * blockDim.x + threadIdx.x;
    if (i >= 256 * Kpad) return;
    int n = i / Kpad, k = i % Kpad;
    float v = 0.f;
    if (k < Kdim) {
        int src = ROT ? (k + AFD) % Kdim : k;
        v = __ldg(&W[(size_t)src * 256 + n]);
    }
    unsigned short h, l; split2(v, h, l);
    hi[i] = __ushort_as_bfloat16(h);
    lo[i] = __ushort_as_bfloat16(l);
}

// ---------------------------------------------------------------------------
// bf16 3-split GEMM via mma.sync with FUSED neighbor gather, sized for
// 2 CTAs/SM: 64x256 CTA tile, 256 threads (8 warps, 1x8 grid, 64x32 warp
// tiles). A double-buffered (hi/lo, SW128); B single-buffered (L2-hot
// weights, reloaded per K-stage via cp.async). A gathered in registers.
// MODE 0: A = fbonds (direct)          -> out1 = C, out2 = relu(C)
// MODE 1: A = gather-sum(bgraph)       -> out1 = relu(binput + C)
// MODE 2: A = [gather-sum(agraph) | fatoms] (K rotated) ->
//            relu(C + bias) atomicAdd into out1[scope[row]]
// ---------------------------------------------------------------------------
#define TILE_M    64
#define A_HL      8192                       // one A half (64 rows x 128B)
#define ABUF(s)   ((uint32_t)((s) & 1) * (2 * A_HL))
#define OFF_ALO   A_HL
#define OFF_BHI   32768
#define OFF_BLO   65536
#define PTR_OFF   98304
#define HG_SMEM   (PTR_OFF + TILE_M * MAXNB * 8)   // 103424

template <int MODE, int KDIM, int NS>
__global__ __launch_bounds__(256, 2)
void hgemm_kernel(const float* __restrict__ Amat,     // MODE0: fbonds, MODE2: fatoms
                  const int*   __restrict__ graph,    // MODE1/2 gather indices
                  const float* __restrict__ tree,
                  const float* __restrict__ msgsrc,
                  const __nv_bfloat16* __restrict__ WThi,
                  const __nv_bfloat16* __restrict__ WTlo,
                  int rowsM,
                  const float* __restrict__ binput,
                  const float* __restrict__ bias,
                  const int*   __restrict__ scope,
                  float* __restrict__ out1,
                  float* __restrict__ out2)
{
    constexpr int KPAD = NS * 64;
    extern __shared__ char smem[];
    const uint32_t sb = smem_u32(smem);
    const int tid  = threadIdx.x;
    const int lane = tid & 31;
    const int wn   = tid >> 5;                         // 1 x 8 warp grid
    const int rowBlock = blockIdx.x * TILE_M;
    const int r = tid >> 2;                            // A-load row (0..63)
    const int q = tid & 3;                             // A-load col quarter (16 cols)

    // ldmatrix lane-address components
    const int arow  = ((lane >> 3) & 1) * 8 + (lane & 7);
    const int akb   = (lane >> 4) * 16;
    const int bnrow = ((lane >> 4) & 1) * 8 + (lane & 7);
    const int bkb   = ((lane >> 3) & 1) * 16;

    // Gather pointer table: TILE_M rows x MAXNB row-base pointers
    const float** ptab = (const float**)(smem + PTR_OFF);
    if (MODE != 0) {
        for (int i = tid; i < TILE_M * MAXNB; i += 256) {
            int rr = i / MAXNB, t = i % MAXNB;
            int grow = rowBlock + rr;
            const float* p = tree;   // tree row 0 is the all-zero pad vector
            if (grow < rowsM) {
                int idx = __ldg(&graph[(size_t)grow * MAXNB + t]);
                p = (idx < M_N) ? tree + (size_t)idx * HDIM
                                : msgsrc + (size_t)(idx - M_N) * HDIM;
            }
            ptab[i] = p;
        }
        __syncthreads();
    }

    float acc[4][4][4];   // [mi][ni(8cols)][quad]
#pragma unroll
    for (int mi = 0; mi < 4; mi++)
#pragma unroll
        for (int ni = 0; ni < 4; ni++)
#pragma unroll
            for (int e = 0; e < 4; e++) acc[mi][ni][e] = 0.f;

    float4 af[4];

    auto ldgA = [&](int s) {
        const int k0 = s * 64;
        const int gr = rowBlock + r;
        const bool gatherSlice = (MODE == 1) || (MODE == 2 && s < 4);
        if (gatherSlice) {
#pragma unroll
            for (int j = 0; j < 4; j++) af[j] = make_float4(0.f, 0.f, 0.f, 0.f);
            const int coff = k0 + q * 16;
#pragma unroll
            for (int t = 0; t < MAXNB; t++) {
                const float4* p = (const float4*)(ptab[r * MAXNB + t] + coff);
#pragma unroll
                for (int j = 0; j < 4; j++) {
                    float4 v = __ldg(p + j);
                    af[j].x += v.x; af[j].y += v.y; af[j].z += v.z; af[j].w += v.w;
                }
            }
        } else if (MODE == 2) {
            // s == 4: fatoms columns (K rotated: col = k - 256)
#pragma unroll
            for (int j = 0; j < 4; j++) {
                float t0 = 0.f, t1 = 0.f, t2 = 0.f, t3 = 0.f;
                int c0 = q * 16 + j * 4;
                if (gr < rowsM) {
                    if (c0 + 0 < AFD) t0 = __ldg(&Amat[(size_t)gr * AFD + c0 + 0]);
                    if (c0 + 1 < AFD) t1 = __ldg(&Amat[(size_t)gr * AFD + c0 + 1]);
                    if (c0 + 2 < AFD) t2 = __ldg(&Amat[(size_t)gr * AFD + c0 + 2]);
                    if (c0 + 3 < AFD) t3 = __ldg(&Amat[(size_t)gr * AFD + c0 + 3]);
                }
                af[j] = make_float4(t0, t1, t2, t3);
            }
        } else {
            // MODE 0: direct rows from Amat [rowsM, KDIM]
#pragma unroll
            for (int j = 0; j < 4; j++) {
                int gc = k0 + q * 16 + j * 4;
                float4 v = make_float4(0.f, 0.f, 0.f, 0.f);
                if (gr < rowsM && gc < KDIM)
                    v = __ldg((const float4*)(Amat + (size_t)gr * KDIM + gc));
                af[j] = v;
            }
        }
    };

    auto stsA = [&](int s) {
        uint32_t bufOff = ABUF(s);
#pragma unroll
        for (int j = 0; j < 4; j++) {
            unsigned short h0, h1, h2, h3, l0, l1, l2, l3;
            split2(af[j].x, h0, l0); split2(af[j].y, h1, l1);
            split2(af[j].z, h2, l2); split2(af[j].w, h3, l3);
            uint2 uh, ul;
            uh.x = (uint32_t)h0 | ((uint32_t)h1 << 16);
            uh.y = (uint32_t)h2 | ((uint32_t)h3 << 16);
            ul.x = (uint32_t)l0 | ((uint32_t)l1 << 16);
            ul.y = (uint32_t)l2 | ((uint32_t)l3 << 16);
            uint32_t off = SW128(r * 128 + q * 32 + j * 8);
            *(uint2*)(smem + bufOff + off)           = uh;
            *(uint2*)(smem + bufOff + OFF_ALO + off) = ul;
        }
    };

    auto cpB = [&](int s) {   // single B buffer, reloaded each stage (L2-hot)
        int k0 = s * 64;
#pragma unroll
        for (int i = 0; i < 8; i++) {
            int idx = i * 256 + tid;                 // 2048 16B-chunks per half
            int n = idx >> 3, c = idx & 7;
            uint32_t dsw = SW128(n * 128 + c * 16);
            const __nv_bfloat16* srch = WThi + (size_t)n * KPAD + k0 + c * 8;
            const __nv_bfloat16* srcl = WTlo + (size_t)n * KPAD + k0 + c * 8;
            cp_async16(sb + OFF_BHI + dsw, srch);
            cp_async16(sb + OFF_BLO + dsw, srcl);
        }
    };

    // Prologue: gather A(0) into registers
    ldgA(0);

    for (int s = 0; s < NS; s++) {
        stsA(s);                    // write A(s) into its own buffer (safe vs MMA(s-1))
        __syncthreads();            // all MMA(s-1) done -> B buffer free; A(s) visible
        cpB(s);                     // refill B (L2-resident weights)
        if (s + 1 < NS) ldgA(s + 1);// prefetch next A gather (overlaps B load + MMA)
        cp_wait_all();
        __syncthreads();            // B(s) visible to all

        const uint32_t aBase = sb + ABUF(s);
#pragma unroll
        for (int kk = 0; kk < 4; kk++) {
#pragma unroll
            for (int nb = 0; nb < 2; nb++) {       // 2 x 16-col blocks
                uint32_t boff = (uint32_t)(wn * 32 + nb * 16 + bnrow) * 128 + kk * 32 + bkb;
                uint32_t bsw = SW128(boff);
                uint32_t bh[4], bl[4];
                ldsm4(bh, sb + OFF_BHI + bsw);
                ldsm4(bl, sb + OFF_BLO + bsw);
#pragma unroll
                for (int mi = 0; mi < 4; mi++) {
                    uint32_t aoff = (uint32_t)(mi * 16 + arow) * 128 + kk * 32 + akb;
                    uint32_t asw = SW128(aoff);
                    uint32_t ahi[4], alo[4];
                    ldsm4(ahi, aBase + asw);
                    ldsm4(alo, aBase + OFF_ALO + asw);
                    mma_bf16(acc[mi][2*nb],   ahi, bh[0], bh[1]);
                    mma_bf16(acc[mi][2*nb+1], ahi, bh[2], bh[3]);
                    mma_bf16(acc[mi][2*nb],   alo, bh[0], bh[1]);
                    mma_bf16(acc[mi][2*nb+1], alo, bh[2], bh[3]);
                    mma_bf16(acc[mi][2*nb],   ahi, bl[0], bl[1]);
                    mma_bf16(acc[mi][2*nb+1], ahi, bl[2], bl[3]);
                }
            }
        }
    }

    // ---- Epilogue: acc in registers ----
#pragma unroll
    for (int mi = 0; mi < 4; mi++) {
        int r0 = rowBlock + mi * 16 + (lane >> 2);
        int r1 = r0 + 8;
        int seg0 = 0, seg1 = 0;
        if (MODE == 2) {
            seg0 = (r0 < rowsM) ? __ldg(&scope[r0]) : 0;
            seg1 = (r1 < rowsM) ? __ldg(&scope[r1]) : 0;
        }
#pragma unroll
        for (int ni = 0; ni < 4; ni++) {
            int col = wn * 32 + ni * 8 + (lane & 3) * 2;
            float* c = acc[mi][ni];
            if (MODE == 0) {
                if (r0 < rowsM) {
                    size_t p = (size_t)r0 * HDIM + col;
                    *(float2*)(out1 + p) = make_float2(c[0], c[1]);
                    *(float2*)(out2 + p) = make_float2(fmaxf(c[0],0.f), fmaxf(c[1],0.f));
                }
                if (r1 < rowsM) {
                    size_t p = (size_t)r1 * HDIM + col;
                    *(float2*)(out1 + p) = make_float2(c[2], c[3]);
                    *(float2*)(out2 + p) = make_float2(fmaxf(c[2],0.f), fmaxf(c[3],0.f));
                }
            } else if (MODE == 1) {
                if (r0 < rowsM) {
                    size_t p = (size_t)r0 * HDIM + col;
                    float2 b = *(const float2*)(binput + p);
                    *(float2*)(out1 + p) = make_float2(fmaxf(c[0]+b.x,0.f), fmaxf(c[1]+b.y,0.f));
                }
                if (r1 < rowsM) {
                    size_t p = (size_t)r1 * HDIM + col;
                    float2 b = *(const float2*)(binput + p);
                    *(float2*)(out1 + p) = make_float2(fmaxf(c[2]+b.x,0.f), fmaxf(c[3]+b.y,0.f));
                }
            } else {
                float b0 = __ldg(&bias[col]), b1 = __ldg(&bias[col + 1]);
                if (r0 < rowsM) {
                    atomicAdd(&out1[(size_t)seg0 * HDIM + col],     fmaxf(c[0] + b0, 0.f));
                    atomicAdd(&out1[(size_t)seg0 * HDIM + col + 1], fmaxf(c[1] + b1, 0.f));
                }
                if (r1 < rowsM) {
                    atomicAdd(&out1[(size_t)seg1 * HDIM + col],     fmaxf(c[2] + b0, 0.f));
                    atomicAdd(&out1[(size_t)seg1 * HDIM + col + 1], fmaxf(c[3] + b1, 0.f));
                }
            }
        }
    }
}

// ---------------------------------------------------------------------------
// Pooling helpers
// ---------------------------------------------------------------------------
__global__ void zero_out_kernel(float* __restrict__ out)
{
    int i = blockIdx.x * blockDim.x + threadIdx.x;
    if (i < NMOLS * HDIM) out[i] = 0.f;
    if (i < NMOLS) g_counts[i] = 0.f;
}
__global__ void count_kernel(const int* __restrict__ scope)
{
    int i = blockIdx.x * blockDim.x + threadIdx.x;
    if (i < A_N) atomicAdd(&g_counts[__ldg(&scope[i])], 1.f);
}
__global__ void finalize_kernel(float* __restrict__ out)
{
    int i = blockIdx.x * blockDim.x + threadIdx.x;
    if (i >= NMOLS * HDIM) return;
    out[i] = out[i] / fmaxf(g_counts[i / HDIM], 1.f);
}

// ---------------------------------------------------------------------------
extern "C" void kernel_launch(void* const* d_in, const int* in_sizes, int n_in,
                              void* d_out, int out_size)
{
    const float* fatoms   = (const float*)d_in[0];
    const float* fbonds   = (const float*)d_in[1];
    const int*   agraph   = (const int*)  d_in[2];
    const int*   bgraph   = (const int*)  d_in[3];
    const float* tree_msg = (const float*)d_in[4];
    const int*   scope    = (const int*)  d_in[5];
    const float* W_i      = (const float*)d_in[6];
    const float* W_h      = (const float*)d_in[7];
    const float* W_o_w    = (const float*)d_in[8];
    const float* W_o_b    = (const float*)d_in[9];
    float* out = (float*)d_out;

    float *binput, *msgA, *msgB;
    __nv_bfloat16 *wthi, *wtlo;
    cudaGetSymbolAddress((void**)&binput, g_binput);
    cudaGetSymbolAddress((void**)&msgA,   g_msgA);
    cudaGetSymbolAddress((void**)&msgB,   g_msgB);
    cudaGetSymbolAddress((void**)&wthi,   g_WThi);
    cudaGetSymbolAddress((void**)&wtlo,   g_WTlo);

    cudaFuncSetAttribute(hgemm_kernel<0, KI,   1>, cudaFuncAttributeMaxDynamicSharedMemorySize, HG_SMEM);
    cudaFuncSetAttribute(hgemm_kernel<1, HDIM, 4>, cudaFuncAttributeMaxDynamicSharedMemorySize, HG_SMEM);
    cudaFuncSetAttribute(hgemm_kernel<2, KO,   5>, cudaFuncAttributeMaxDynamicSharedMemorySize, HG_SMEM);

    const int gridB = (B_N + TILE_M - 1) / TILE_M;   // 3125
    const int gridA = (A_N + TILE_M - 1) / TILE_M;   // 1563

    // 1) binput = fbonds @ W_i ; msgA = relu(binput)
    prep_w_kernel<0><<<(256 * 64 + 255) / 256, 256>>>(W_i, KI, 64, wthi, wtlo);
    hgemm_kernel<0, KI, 1><<<gridB, 256, HG_SMEM>>>(
        fbonds, nullptr, tree_msg, nullptr, wthi, wtlo, B_N,
        nullptr, nullptr, nullptr, binput, msgA);

    // 2) two message-passing iterations, gather fused into GEMM A-load
    prep_w_kernel<0><<<(256 * 256 + 255) / 256, 256>>>(W_h, HDIM, 256, wthi, wtlo);
    hgemm_kernel<1, HDIM, 4><<<gridB, 256, HG_SMEM>>>(
        nullptr, bgraph, tree_msg, msgA, wthi, wtlo, B_N,
        binput, nullptr, nullptr, msgB, nullptr);
    hgemm_kernel<1, HDIM, 4><<<gridB, 256, HG_SMEM>>>(
        nullptr, bgraph, tree_msg, msgB, wthi, wtlo, B_N,
        binput, nullptr, nullptr, msgA, nullptr);

    // 3) pooling prep + output GEMM with fused atom gather + segment-sum
    zero_out_kernel<<<(NMOLS * HDIM + 255) / 256, 256>>>(out);
    count_kernel<<<(A_N + 255) / 256, 256>>>(scope);
    prep_w_kernel<1><<<(256 * 320 + 255) / 256, 256>>>(W_o_w, KO, 320, wthi, wtlo);
    hgemm_kernel<2, KO, 5><<<gridA, 256, HG_SMEM>>>(
        fatoms, agraph, tree_msg, msgA, wthi, wtlo, A_N,
        nullptr, W_o_b, scope, out, nullptr);
    finalize_kernel<<<(NMOLS * HDIM + 255) / 256, 256>>>(out);
}

// round 8
// speedup vs baseline: 2.4695x; 1.3311x over previous
#include <cuda_runtime.h>
#include <cuda_bf16.h>
#include <cstdint>

// Problem constants
#define A_N   100000
#define B_N   200000
#define M_N   20000
#define HDIM  256
#define MAXNB 10
#define NMOLS 2000
#define AFD   35
#define KI    40    // fbonds @ W_i
#define KO    291   // [fatoms, nei] @ W_o_w

// Scratch (device globals)
__device__ float g_binput[(size_t)B_N * HDIM];
__device__ float g_msg   [(size_t)B_N * HDIM];
__device__ float g_counts[NMOLS];
// Split bf16 operand buffers
__device__ __nv_bfloat16 g_neihi[(size_t)B_N * HDIM];
__device__ __nv_bfloat16 g_neilo[(size_t)B_N * HDIM];
__device__ __nv_bfloat16 g_fbhi [(size_t)B_N * 64];
__device__ __nv_bfloat16 g_fblo [(size_t)B_N * 64];
__device__ __nv_bfloat16 g_fahi [(size_t)A_N * 64];
__device__ __nv_bfloat16 g_falo [(size_t)A_N * 64];
// Pre-transposed, bf16-split weights: [N=256, KPAD<=320]
__device__ __nv_bfloat16 g_WThi[256 * 320];
__device__ __nv_bfloat16 g_WTlo[256 * 320];

// ---------------------------------------------------------------------------
// Helpers (base-sm_103-legal: ldmatrix / mma.sync / cp.async)
// ---------------------------------------------------------------------------
__device__ __forceinline__ uint32_t smem_u32(const void* p) {
    uint32_t a;
    asm("{ .reg .u64 t; cvta.to.shared.u64 t, %1; cvt.u32.u64 %0, t; }" : "=r"(a) : "l"(p));
    return a;
}
__device__ __forceinline__ void ldsm4(uint32_t* r, uint32_t addr) {
    asm volatile("ldmatrix.sync.aligned.m8n8.x4.shared.b16 {%0,%1,%2,%3}, [%4];"
                 : "=r"(r[0]), "=r"(r[1]), "=r"(r[2]), "=r"(r[3]) : "r"(addr));
}
__device__ __forceinline__ void mma_bf16(float* c, const uint32_t* a, uint32_t b0, uint32_t b1) {
    asm volatile("mma.sync.aligned.m16n8k16.row.col.f32.bf16.bf16.f32 "
                 "{%0,%1,%2,%3},{%4,%5,%6,%7},{%8,%9},{%0,%1,%2,%3};"
                 : "+f"(c[0]), "+f"(c[1]), "+f"(c[2]), "+f"(c[3])
                 : "r"(a[0]), "r"(a[1]), "r"(a[2]), "r"(a[3]), "r"(b0), "r"(b1));
}
__device__ __forceinline__ void cp_async16(uint32_t dst, const void* src) {
    asm volatile("cp.async.cg.shared.global [%0], [%1], 16;" :: "r"(dst), "l"(src));
}
__device__ __forceinline__ void cp_commit() {
    asm volatile("cp.async.commit_group;" ::: "memory");
}
template <int N>
__device__ __forceinline__ void cp_wait_group() {
    asm volatile("cp.async.wait_group %0;" :: "n"(N) : "memory");
}

#define SW128(o) ((o) ^ ((((uint32_t)(o)) >> 3) & 0x70))

__device__ __forceinline__ void split2(float v, unsigned short& h, unsigned short& l) {
    __nv_bfloat16 hb = __float2bfloat16_rn(v);
    float rem = v - __bfloat162float(hb);
    h = __bfloat16_as_ushort(hb);
    l = __bfloat16_as_ushort(__float2bfloat16_rn(rem));
}

// ---------------------------------------------------------------------------
// Gather + sum over MAX_NB neighbor rows of virtual concat [tree ; msg],
// emitting the bf16 hi/lo split of the fp32 sum (same write bytes).
// ---------------------------------------------------------------------------
__global__ void gather_split_kernel(const int* __restrict__ graph, int rows,
                                    const float* __restrict__ tree,
                                    const float* __restrict__ msg,
                                    __nv_bfloat16* __restrict__ outhi,
                                    __nv_bfloat16* __restrict__ outlo)
{
    int row = blockIdx.x * blockDim.y + threadIdx.y;
    if (row >= rows) return;
    int t = threadIdx.x;  // 0..63
    const int* gr = graph + (size_t)row * MAXNB;
    float4 acc = make_float4(0.f, 0.f, 0.f, 0.f);
#pragma unroll
    for (int j = 0; j < MAXNB; j++) {
        int idx = __ldg(&gr[j]);
        const float* srcp = (idx < M_N) ? (tree + (size_t)idx * HDIM)
                                        : (msg  + (size_t)(idx - M_N) * HDIM);
        float4 v = __ldg(((const float4*)srcp) + t);
        acc.x += v.x; acc.y += v.y; acc.z += v.z; acc.w += v.w;
    }
    unsigned short h0,h1,h2,h3,l0,l1,l2,l3;
    split2(acc.x,h0,l0); split2(acc.y,h1,l1); split2(acc.z,h2,l2); split2(acc.w,h3,l3);
    uint2 uh, ul;
    uh.x = (uint32_t)h0 | ((uint32_t)h1 << 16);
    uh.y = (uint32_t)h2 | ((uint32_t)h3 << 16);
    ul.x = (uint32_t)l0 | ((uint32_t)l1 << 16);
    ul.y = (uint32_t)l2 | ((uint32_t)l3 << 16);
    ((uint2*)outhi)[(size_t)row * 64 + t] = uh;
    ((uint2*)outlo)[(size_t)row * 64 + t] = ul;
}

// ---------------------------------------------------------------------------
// Prep: fp32 [rows, inK] -> bf16 hi/lo [rows, 64] zero-padded
// ---------------------------------------------------------------------------
__global__ void prep_a_kernel(const float* __restrict__ in, int rows, int inK,
                              __nv_bfloat16* __restrict__ hi, __nv_bfloat16* __restrict__ lo)
{
    size_t i = (size_t)blockIdx.x * blockDim.x + threadIdx.x;
    if (i >= (size_t)rows * 64) return;
    int r = (int)(i >> 6), k = (int)(i & 63);
    float v = (k < inK) ? __ldg(&in[(size_t)r * inK + k]) : 0.f;
    unsigned short h, l; split2(v, h, l);
    hi[i] = __ushort_as_bfloat16(h);
    lo[i] = __ushort_as_bfloat16(l);
}

// ---------------------------------------------------------------------------
// Weight prep: W [Kdim, 256] fp32 -> WT hi/lo bf16 [256, Kpad] (zero padded).
// ROT=1: source row = (k + AFD) % Kdim -> [nei | fatoms] ordering.
// ---------------------------------------------------------------------------
template <int ROT>
__global__ void prep_w_kernel(const float* __restrict__ W, int Kdim, int Kpad,
                              __nv_bfloat16* __restrict__ hi, __nv_bfloat16* __restrict__ lo)
{
    int i = blockIdx.x * blockDim.x + threadIdx.x;
    if (i >= 256 * Kpad) return;
    int n = i / Kpad, k = i % Kpad;
    float v = 0.f;
    if (k < Kdim) {
        int src = ROT ? (k + AFD) % Kdim : k;
        v = __ldg(&W[(size_t)src * 256 + n]);
    }
    unsigned short h, l; split2(v, h, l);
    hi[i] = __ushort_as_bfloat16(h);
    lo[i] = __ushort_as_bfloat16(l);
}

// ---------------------------------------------------------------------------
// Pure bf16 3-split HGEMM: C[64,256] tiles; A and B both via cp.async from
// pre-split bf16 buffers. 256 threads, 8 warps (1x8), 64x32 warp tiles.
// A double-buffered (hi+lo 16KB/buf), B single-buffered (64KB, L2-hot),
// 96KB smem total -> 2 CTAs/SM.
// MODE 0: out1 = C (binput), out2 = relu(C) (msg)
// MODE 1: out1 = relu(binput + C) (msg)
// MODE 2: relu(C + bias) atomicAdd into out1[scope[row]]; A stage NS-1
//         comes from (A2hi,A2lo,strideA2) [fatoms], earlier stages from nei.
// ---------------------------------------------------------------------------
#define TILE_M   64
#define ABUF(s)  ((uint32_t)((s) & 1) * 16384)
#define A_LO_OFF 8192
#define B_HI     32768
#define B_LO     65536
#define HG_SMEM  98304

template <int MODE, int NS>
__global__ __launch_bounds__(256, 2)
void hgemm_kernel(const __nv_bfloat16* __restrict__ Ahi,
                  const __nv_bfloat16* __restrict__ Alo,
                  int strideA,
                  const __nv_bfloat16* __restrict__ A2hi,
                  const __nv_bfloat16* __restrict__ A2lo,
                  int strideA2,
                  const __nv_bfloat16* __restrict__ WThi,
                  const __nv_bfloat16* __restrict__ WTlo,
                  int rowsM,
                  const float* __restrict__ binput,
                  const float* __restrict__ bias,
                  const int*   __restrict__ scope,
                  float* __restrict__ out1,
                  float* __restrict__ out2)
{
    constexpr int KPAD = NS * 64;
    extern __shared__ char smem[];
    const uint32_t sb = smem_u32(smem);
    const int tid  = threadIdx.x;
    const int lane = tid & 31;
    const int wn   = tid >> 5;                 // 1 x 8 warp grid
    const int rowBlock = blockIdx.x * TILE_M;

    // ldmatrix lane-address components
    const int arow  = ((lane >> 3) & 1) * 8 + (lane & 7);
    const int akb   = (lane >> 4) * 16;
    const int bnrow = ((lane >> 4) & 1) * 8 + (lane & 7);
    const int bkb   = ((lane >> 3) & 1) * 16;

    float acc[4][4][4];   // [mi][ni(8cols)][quad]
#pragma unroll
    for (int mi = 0; mi < 4; mi++)
#pragma unroll
        for (int ni = 0; ni < 4; ni++)
#pragma unroll
            for (int e = 0; e < 4; e++) acc[mi][ni][e] = 0.f;

    auto cpA = [&](int s) {   // 64 rows x 64 cols bf16 (hi+lo), SW128
        const __nv_bfloat16 *sh, *sl;
        int stride, kk0;
        if (MODE == 2 && s == NS - 1) { sh = A2hi; sl = A2lo; stride = strideA2; kk0 = 0; }
        else                          { sh = Ahi;  sl = Alo;  stride = strideA;  kk0 = s * 64; }
        uint32_t abuf = ABUF(s);
#pragma unroll
        for (int i = 0; i < 2; i++) {
            int idx = i * 256 + tid;          // 512 16B-chunks per half
            int r = idx >> 3, c = idx & 7;
            int grow = rowBlock + r;
            if (grow >= rowsM) grow = rowsM - 1;   // clamp; epilogue guards stores
            uint32_t dsw = SW128(r * 128 + c * 16);
            size_t src = (size_t)grow * stride + kk0 + c * 8;
            cp_async16(sb + abuf + dsw,            sh + src);
            cp_async16(sb + abuf + A_LO_OFF + dsw, sl + src);
        }
    };

    auto cpB = [&](int s) {   // 256 n-rows x 64 k-cols bf16 (hi+lo), SW128
        int k0 = s * 64;
#pragma unroll
        for (int i = 0; i < 8; i++) {
            int idx = i * 256 + tid;          // 2048 16B-chunks per half
            int n = idx >> 3, c = idx & 7;
            uint32_t dsw = SW128(n * 128 + c * 16);
            size_t src = (size_t)n * KPAD + k0 + c * 8;
            cp_async16(sb + B_HI + dsw, WThi + src);
            cp_async16(sb + B_LO + dsw, WTlo + src);
        }
    };

    // Prologue: A(0) in flight as its own group
    cpA(0);
    cp_commit();

    for (int s = 0; s < NS; s++) {
        __syncthreads();            // MMA(s-1) done: B buffer + A[(s+1)&1] free
        cpB(s);
        cp_commit();
        if (s + 1 < NS) {
            cpA(s + 1);
            cp_commit();
            cp_wait_group<1>();     // A(s), B(s) arrived; A(s+1) may be pending
        } else {
            cp_wait_group<0>();
        }
        __syncthreads();

        const uint32_t aBase = sb + ABUF(s);
#pragma unroll
        for (int kk = 0; kk < 4; kk++) {
#pragma unroll
            for (int nb = 0; nb < 2; nb++) {
                uint32_t boff = (uint32_t)(wn * 32 + nb * 16 + bnrow) * 128 + kk * 32 + bkb;
                uint32_t bsw = SW128(boff);
                uint32_t bh[4], bl[4];
                ldsm4(bh, sb + B_HI + bsw);
                ldsm4(bl, sb + B_LO + bsw);
#pragma unroll
                for (int mi = 0; mi < 4; mi++) {
                    uint32_t aoff = (uint32_t)(mi * 16 + arow) * 128 + kk * 32 + akb;
                    uint32_t asw = SW128(aoff);
                    uint32_t ahi[4], alo[4];
                    ldsm4(ahi, aBase + asw);
                    ldsm4(alo, aBase + A_LO_OFF + asw);
                    mma_bf16(acc[mi][2*nb],   ahi, bh[0], bh[1]);
                    mma_bf16(acc[mi][2*nb+1], ahi, bh[2], bh[3]);
                    mma_bf16(acc[mi][2*nb],   alo, bh[0], bh[1]);
                    mma_bf16(acc[mi][2*nb+1], alo, bh[2], bh[3]);
                    mma_bf16(acc[mi][2*nb],   ahi, bl[0], bl[1]);
                    mma_bf16(acc[mi][2*nb+1], ahi, bl[2], bl[3]);
                }
            }
        }
    }

    // ---- Epilogue ----
#pragma unroll
    for (int mi = 0; mi < 4; mi++) {
        int r0 = rowBlock + mi * 16 + (lane >> 2);
        int r1 = r0 + 8;
        int seg0 = 0, seg1 = 0;
        if (MODE == 2) {
            seg0 = (r0 < rowsM) ? __ldg(&scope[r0]) : 0;
            seg1 = (r1 < rowsM) ? __ldg(&scope[r1]) : 0;
        }
#pragma unroll
        for (int ni = 0; ni < 4; ni++) {
            int col = wn * 32 + ni * 8 + (lane & 3) * 2;
            float* c = acc[mi][ni];
            if (MODE == 0) {
                if (r0 < rowsM) {
                    size_t p = (size_t)r0 * HDIM + col;
                    *(float2*)(out1 + p) = make_float2(c[0], c[1]);
                    *(float2*)(out2 + p) = make_float2(fmaxf(c[0],0.f), fmaxf(c[1],0.f));
                }
                if (r1 < rowsM) {
                    size_t p = (size_t)r1 * HDIM + col;
                    *(float2*)(out1 + p) = make_float2(c[2], c[3]);
                    *(float2*)(out2 + p) = make_float2(fmaxf(c[2],0.f), fmaxf(c[3],0.f));
                }
            } else if (MODE == 1) {
                if (r0 < rowsM) {
                    size_t p = (size_t)r0 * HDIM + col;
                    float2 b = *(const float2*)(binput + p);
                    *(float2*)(out1 + p) = make_float2(fmaxf(c[0]+b.x,0.f), fmaxf(c[1]+b.y,0.f));
                }
                if (r1 < rowsM) {
                    size_t p = (size_t)r1 * HDIM + col;
                    float2 b = *(const float2*)(binput + p);
                    *(float2*)(out1 + p) = make_float2(fmaxf(c[2]+b.x,0.f), fmaxf(c[3]+b.y,0.f));
                }
            } else {
                float b0 = __ldg(&bias[col]), b1 = __ldg(&bias[col + 1]);
                if (r0 < rowsM) {
                    atomicAdd(&out1[(size_t)seg0 * HDIM + col],     fmaxf(c[0] + b0, 0.f));
                    atomicAdd(&out1[(size_t)seg0 * HDIM + col + 1], fmaxf(c[1] + b1, 0.f));
                }
                if (r1 < rowsM) {
                    atomicAdd(&out1[(size_t)seg1 * HDIM + col],     fmaxf(c[2] + b0, 0.f));
                    atomicAdd(&out1[(size_t)seg1 * HDIM + col + 1], fmaxf(c[3] + b1, 0.f));
                }
            }
        }
    }
}

// ---------------------------------------------------------------------------
// Pooling helpers
// ---------------------------------------------------------------------------
__global__ void zero_out_kernel(float* __restrict__ out)
{
    int i = blockIdx.x * blockDim.x + threadIdx.x;
    if (i < NMOLS * HDIM) out[i] = 0.f;
    if (i < NMOLS) g_counts[i] = 0.f;
}
__global__ void count_kernel(const int* __restrict__ scope)
{
    int i = blockIdx.x * blockDim.x + threadIdx.x;
    if (i < A_N) atomicAdd(&g_counts[__ldg(&scope[i])], 1.f);
}
__global__ void finalize_kernel(float* __restrict__ out)
{
    int i = blockIdx.x * blockDim.x + threadIdx.x;
    if (i >= NMOLS * HDIM) return;
    out[i] = out[i] / fmaxf(g_counts[i / HDIM], 1.f);
}

// ---------------------------------------------------------------------------
extern "C" void kernel_launch(void* const* d_in, const int* in_sizes, int n_in,
                              void* d_out, int out_size)
{
    const float* fatoms   = (const float*)d_in[0];
    const float* fbonds   = (const float*)d_in[1];
    const int*   agraph   = (const int*)  d_in[2];
    const int*   bgraph   = (const int*)  d_in[3];
    const float* tree_msg = (const float*)d_in[4];
    const int*   scope    = (const int*)  d_in[5];
    const float* W_i      = (const float*)d_in[6];
    const float* W_h      = (const float*)d_in[7];
    const float* W_o_w    = (const float*)d_in[8];
    const float* W_o_b    = (const float*)d_in[9];
    float* out = (float*)d_out;

    float *binput, *msg;
    __nv_bfloat16 *neihi, *neilo, *fbhi, *fblo, *fahi, *falo, *wthi, *wtlo;
    cudaGetSymbolAddress((void**)&binput, g_binput);
    cudaGetSymbolAddress((void**)&msg,    g_msg);
    cudaGetSymbolAddress((void**)&neihi,  g_neihi);
    cudaGetSymbolAddress((void**)&neilo,  g_neilo);
    cudaGetSymbolAddress((void**)&fbhi,   g_fbhi);
    cudaGetSymbolAddress((void**)&fblo,   g_fblo);
    cudaGetSymbolAddress((void**)&fahi,   g_fahi);
    cudaGetSymbolAddress((void**)&falo,   g_falo);
    cudaGetSymbolAddress((void**)&wthi,   g_WThi);
    cudaGetSymbolAddress((void**)&wtlo,   g_WTlo);

    cudaFuncSetAttribute(hgemm_kernel<0, 1>, cudaFuncAttributeMaxDynamicSharedMemorySize, HG_SMEM);
    cudaFuncSetAttribute(hgemm_kernel<1, 4>, cudaFuncAttributeMaxDynamicSharedMemorySize, HG_SMEM);
    cudaFuncSetAttribute(hgemm_kernel<2, 5>, cudaFuncAttributeMaxDynamicSharedMemorySize, HG_SMEM);

    const int gridB = (B_N + TILE_M - 1) / TILE_M;   // 3125
    const int gridA = (A_N + TILE_M - 1) / TILE_M;   // 1563
    dim3 gblk(64, 4);

    // 1) prep fbonds split + W_i ; binput = fbonds @ W_i ; msg = relu(binput)
    prep_a_kernel<<<(int)(((size_t)B_N * 64 + 255) / 256), 256>>>(fbonds, B_N, KI, fbhi, fblo);
    prep_w_kernel<0><<<(256 * 64 + 255) / 256, 256>>>(W_i, KI, 64, wthi, wtlo);
    hgemm_kernel<0, 1><<<gridB, 256, HG_SMEM>>>(
        fbhi, fblo, 64, nullptr, nullptr, 0, wthi, wtlo, B_N,
        nullptr, nullptr, nullptr, binput, msg);

    // 2) two message-passing iterations: standalone gather (split out) + GEMM
    prep_w_kernel<0><<<(256 * 256 + 255) / 256, 256>>>(W_h, HDIM, 256, wthi, wtlo);
    for (int d = 0; d < 2; d++) {
        gather_split_kernel<<<(B_N + 3) / 4, gblk>>>(bgraph, B_N, tree_msg, msg, neihi, neilo);
        hgemm_kernel<1, 4><<<gridB, 256, HG_SMEM>>>(
            neihi, neilo, HDIM, nullptr, nullptr, 0, wthi, wtlo, B_N,
            binput, nullptr, nullptr, msg, nullptr);
    }

    // 3) atom gather (split out) + pooling prep + output GEMM (fused seg-sum)
    gather_split_kernel<<<(A_N + 3) / 4, gblk>>>(agraph, A_N, tree_msg, msg, neihi, neilo);
    zero_out_kernel<<<(NMOLS * HDIM + 255) / 256, 256>>>(out);
    count_kernel<<<(A_N + 255) / 256, 256>>>(scope);
    prep_a_kernel<<<(int)(((size_t)A_N * 64 + 255) / 256), 256>>>(fatoms, A_N, AFD, fahi, falo);
    prep_w_kernel<1><<<(256 * 320 + 255) / 256, 256>>>(W_o_w, KO, 320, wthi, wtlo);
    hgemm_kernel<2, 5><<<gridA, 256, HG_SMEM>>>(
        neihi, neilo, HDIM, fahi, falo, 64, wthi, wtlo, A_N,
        nullptr, W_o_b, scope, out, nullptr);
    finalize_kernel<<<(NMOLS * HDIM + 255) / 256, 256>>>(out);
}